// round 16
// baseline (speedup 1.0000x reference)
#include <cuda_runtime.h>

#define Tn   720
#define Bn   512
#define INn  6
#define Hn   128
#define OUTn 3
#define HORn 360
#define NBLK 148
#define NTHR 512
#define CHK  128
#define STRD 132   // [b][kk] staging stride: 33*16B -> conflict-free LDS.128

typedef unsigned long long ull;

struct Params {
    const float* x;
    const float* wih[6];   // e0f,e0b,e1f,e1b,d0,d1
    const float* whh[6];
    const float* bih[6];
    const float* bhh[6];
    const float* brh_W; const float* brh_b;
    const float* brc_W; const float* brc_b;
    const float* out_W; const float* out_b;
    const float* start;
    float* out;
};

// ---------------- scratch (device globals; no allocation allowed) ----------------
__device__ float g_y0[(size_t)Tn * Bn * 2 * Hn];      // encoder layer0 outputs [t][b][256]
__device__ float g_h[2][6][Bn][Hn];                   // double-buffered hidden state
__device__ float g_c[6][Bn][Hn];                      // cell state (in-place)
__device__ float g_hp[2][16][8][32][OUTn];            // decoder head partials [parity][grp][jb][b][o]
__device__ unsigned g_barcnt = 0;
__device__ unsigned g_bargen = 0;
__device__ unsigned g_gcnt[16 * 32];                  // monotonic arrival counts, 128B apart
__device__ unsigned g_ggen[16 * 32];                  // published completed-round counts

// ---------------- shared-memory layout (dynamic, ~167KB) ----------------
#define SW_FLOATS (387 * 64)            // weights [row][jloc*4+gate], 16 j per block
#define SA_FLOATS (64 * STRD)           // one staging buffer: 64 b x 128 kk (+pad)
#define SB_OFF    (SW_FLOATS + 2 * SA_FLOATS)
#define SMEM_BYTES ((SB_OFF + 128) * 4)

// ---------------- cp.async helpers ----------------
__device__ __forceinline__ void cp16(unsigned saddr, const float* g) {
    asm volatile("cp.async.ca.shared.global [%0], [%1], 16;" :: "r"(saddr), "l"(g));
}
#define CP_COMMIT() asm volatile("cp.async.commit_group;" ::: "memory")
#define CP_WAIT0()  asm volatile("cp.async.wait_group 0;" ::: "memory")

// ---------------- full grid barrier (phase boundaries only) ----------------
__device__ __forceinline__ void gbar() {
    __syncthreads();
    if (threadIdx.x == 0) {
        volatile unsigned* vg = &g_bargen;
        unsigned gen = *vg;
        __threadfence();
        if (atomicAdd(&g_barcnt, 1u) == NBLK - 1) {
            g_barcnt = 0;
            __threadfence();
            *vg = gen + 1;
        } else {
            while (*vg == gen) { __nanosleep(32); }
        }
        __threadfence();
    }
    __syncthreads();
}

// ---------------- split 8-block group barrier (monotonic rounds) ----------------
// Counters RESET each launch in Phase 0 (graph-replay determinism).
__device__ __forceinline__ void gb_arrive(int g) {
    __syncthreads();                           // all epilogue stores issued
    if (threadIdx.x == 0) {
        __threadfence();                       // release h/partial stores
        unsigned old = atomicAdd(&g_gcnt[g * 32], 1u);
        if (((old + 1) & 7u) == 0u) {          // 8th arrival of this round
            __threadfence();
            *(volatile unsigned*)&g_ggen[g * 32] = (old + 1) >> 3;
        }
    }
}
__device__ __forceinline__ void gb_wait(int g, unsigned target) {
    if (threadIdx.x == 0) {
        volatile unsigned* vg = &g_ggen[g * 32];
        while (*vg < target) { __nanosleep(20); }
        __threadfence();                       // acquire: invalidate L1
    }
    __syncthreads();
}

// ---------------- fast activations ----------------
__device__ __forceinline__ float sigf(float x) {
    return __fdividef(1.f, 1.f + __expf(-x));
}
__device__ __forceinline__ float tanhfast(float x) {
    return 1.f - __fdividef(2.f, __expf(2.f * x) + 1.f);
}

// ---------------- per-phase weight packing into smem ----------------
__device__ void pack_cell(float* __restrict__ s_w, float* __restrict__ s_bias,
                          const float* __restrict__ wih, const float* __restrict__ whh,
                          const float* __restrict__ bih, const float* __restrict__ bhh,
                          int Kin, int j0, int rowBase, int biasSlot)
{
    int total = (Kin + Hn) * 64;
    for (int e = threadIdx.x; e < total; e += NTHR) {
        int row = e >> 6, c = e & 63;
        int j = j0 + (c >> 2), g = c & 3;
        float v = (row < Kin) ? wih[(g * Hn + j) * Kin + row]
                              : whh[(g * Hn + j) * Hn + (row - Kin)];
        s_w[(size_t)(rowBase + row) * 64 + c] = v;
    }
    for (int e = threadIdx.x; e < 64; e += NTHR) {
        int j = j0 + (e >> 2), g = e & 3;
        s_bias[biasSlot * 64 + e] = bih[g * Hn + j] + bhh[g * Hn + j];
    }
}

struct Chunk { const float* src; long str; int kc; int wrow; };

// ---------------- fused LSTM cell tile ----------------
// Tile: BT b x 16 j with 512 threads (16 warps). Warps split as (16/JPT)
// j-groups x (BT/32) b-halves: warp w -> jq = w/BH, bh = w%BH. Thread owns
// 1 b (bh*32+lane) and JPT adjacent j. Same per-thread inner shape as the
// proven R13 loop; 2x the warps for latency coverage.
// Encoder: BT=64, JPT=2. Decoder: BT=32, JPT=1.
template<int BT, int JPT>
__device__ void cell_tile(float* __restrict__ s_w, float* __restrict__ s_a,
                          const float* __restrict__ s_bias,
                          int b0, int j0g,
                          const float* __restrict__ A, long aStr, long aOff, int Kin, int rowBase,
                          const float* __restrict__ hsrc, float* __restrict__ hdst,
                          float* __restrict__ cst, float* __restrict__ yout, int yStr,
                          int g, unsigned waitRound, bool hFirst,
                          int xinMode, const float* __restrict__ hpIn,
                          const float* __restrict__ xvec, float* __restrict__ poutPrev,
                          float* __restrict__ hpOut, const float* __restrict__ outW)
{
    constexpr int BH = BT / 32;           // b-halves (warps per j-group)
    static_assert((16 / JPT) * BH == NTHR / 32, "warps must cover 16 j x BT b");
    const int tid  = threadIdx.x;
    const int lane = tid & 31;
    const int w    = tid >> 5;
    const int jq   = w / BH;              // j-group
    const int bh   = w % BH;              // b-half
    const int bloc = bh * 32 + lane;      // b within tile
    const int j0l  = jq * JPT;
    const int jgl  = j0g + j0l;
    const unsigned sa0 = (unsigned)__cvta_generic_to_shared(s_a);

    ull accL[JPT], accH[JPT];             // per j: packed (i,f) and (g,o)
#pragma unroll
    for (int jj = 0; jj < JPT; jj++) {
        ulonglong2 bj = *(const ulonglong2*)&s_bias[(j0l + jj) * 4];
        accL[jj] = bj.x; accH[jj] = bj.y;
    }

    // ---- build chunk list, dependent chunk(s) last ----
    Chunk ch[3]; int nch = 0;
    if (hFirst) {
        ch[nch++] = { hsrc + (long)b0 * Hn, (long)Hn, CHK, rowBase + Kin };
        ch[nch++] = { A + (long)b0 * aStr + aOff, aStr,
                      (Kin < CHK) ? Kin : CHK, rowBase };
    } else {
        for (int k0 = 0; k0 < Kin; k0 += CHK) {
            int kc = (Kin - k0 < CHK) ? (Kin - k0) : CHK;
            ch[nch].src = A + (long)b0 * aStr + aOff + k0;
            ch[nch].str = aStr; ch[nch].kc = kc; ch[nch].wrow = rowBase + k0;
            nch++;
        }
        ch[nch++] = { hsrc + (long)b0 * Hn, (long)Hn, CHK, rowBase + Kin };
    }

    auto stage_async = [&](const Chunk& c, int buf) {
#pragma unroll
        for (int u = 0; u < BT * 32 / NTHR; u++) {
            int q = tid + u * NTHR;       // quad index: b = q>>5, kq = q&31
            int b = q >> 5, kq = q & 31;
            cp16(sa0 + (unsigned)(buf * SA_FLOATS + b * STRD + kq * 4) * 4u,
                 c.src + (long)b * c.str + kq * 4);
        }
        CP_COMMIT();
    };
    // scalar staging for small chunks (K = 6 or 3); handles xin modes
    auto stage_small = [&](const Chunk& c, int buf) {
        if (xinMode == 2) {
            for (int idx = tid; idx < BT * c.kc; idx += NTHR) {
                int b = idx / c.kc, kk = idx - b * c.kc;
                s_a[buf * SA_FLOATS + b * STRD + kk] = xvec[kk];
            }
        } else if (xinMode == 1) {
            for (int idx = tid; idx < BT * OUTn; idx += NTHR) {
                int b = idx / OUTn, o = idx - b * OUTn;
                float v = xvec[o];
#pragma unroll
                for (int jb = 0; jb < 8; jb++)
                    v += hpIn[(jb * 32 + b) * OUTn + o];
                s_a[buf * SA_FLOATS + b * STRD + o] = v;
                if (poutPrev)
                    poutPrev[(size_t)(b0 + b) * HORn * OUTn + o] = v;
            }
        } else {
            for (int idx = tid; idx < BT * c.kc; idx += NTHR) {
                int b = idx / c.kc, kk = idx - b * c.kc;
                s_a[buf * SA_FLOATS + b * STRD + kk] = c.src[(long)b * c.str + kk];
            }
        }
    };

    // chunk 0 into buffer 0 (always independent — no wait needed)
    if (ch[0].kc == CHK) { stage_async(ch[0], 0); CP_WAIT0(); }
    else                 { stage_small(ch[0], 0); }
    __syncthreads();

#pragma unroll 1
    for (int i = 0; i < nch; i++) {
        if (i + 1 < nch) {
            if (i + 1 == nch - 1) gb_wait(g, waitRound);   // dep chunk: wait first
            if (ch[i + 1].kc == CHK) stage_async(ch[i + 1], (i + 1) & 1);
            else                     stage_small(ch[i + 1], (i + 1) & 1);
        }

        const int kc = ch[i].kc;
        const float* wp = s_w + (size_t)ch[i].wrow * 64 + jq * (JPT * 4);
        const float* ab = s_a + (i & 1) * SA_FLOATS + bloc * STRD;
        if (kc == CHK) {
#pragma unroll 2
            for (int kq = 0; kq < CHK; kq += 4) {
                float4 av = *(const float4*)&ab[kq];
#pragma unroll
                for (int t = 0; t < 4; t++) {
                    float a = (t == 0) ? av.x : (t == 1) ? av.y : (t == 2) ? av.z : av.w;
                    ull a2; asm("mov.b64 %0,{%1,%1};" : "=l"(a2) : "f"(a));
                    const float* wr = wp + (size_t)(kq + t) * 64;
#pragma unroll
                    for (int jj = 0; jj < JPT; jj++) {
                        ulonglong2 wv = *(const ulonglong2*)(wr + jj * 4);
                        asm("fma.rn.f32x2 %0,%1,%2,%0;" : "+l"(accL[jj]) : "l"(a2), "l"(wv.x));
                        asm("fma.rn.f32x2 %0,%1,%2,%0;" : "+l"(accH[jj]) : "l"(a2), "l"(wv.y));
                    }
                }
            }
        } else {
            for (int kk = 0; kk < kc; kk++) {
                float a = ab[kk];
                ull a2; asm("mov.b64 %0,{%1,%1};" : "=l"(a2) : "f"(a));
                const float* wr = wp + (size_t)kk * 64;
#pragma unroll
                for (int jj = 0; jj < JPT; jj++) {
                    ulonglong2 wv = *(const ulonglong2*)(wr + jj * 4);
                    asm("fma.rn.f32x2 %0,%1,%2,%0;" : "+l"(accL[jj]) : "l"(a2), "l"(wv.x));
                    asm("fma.rn.f32x2 %0,%1,%2,%0;" : "+l"(accH[jj]) : "l"(a2), "l"(wv.y));
                }
            }
        }

        if (i + 1 < nch) { CP_WAIT0(); __syncthreads(); }
    }

    // gate update — thread exclusively owns (bloc, jgl..jgl+JPT-1)
    int b = b0 + bloc;
    long ci = (long)b * Hn + jgl;
    float cold[JPT], cn[JPT], hn[JPT];
    if (JPT == 2) {
        float2 t = *(const float2*)&cst[ci];
        cold[0] = t.x; cold[1] = t.y;
    } else {
        cold[0] = cst[ci];
    }
#pragma unroll
    for (int jj = 0; jj < JPT; jj++) {
        float gi, gf, gg, go;
        asm("mov.b64 {%0,%1},%2;" : "=f"(gi), "=f"(gf) : "l"(accL[jj]));
        asm("mov.b64 {%0,%1},%2;" : "=f"(gg), "=f"(go) : "l"(accH[jj]));
        cn[jj] = sigf(gf) * cold[jj] + sigf(gi) * tanhfast(gg);
        hn[jj] = sigf(go) * tanhfast(cn[jj]);
    }
    if (JPT == 2) {
        *(float2*)&cst[ci]  = make_float2(cn[0], cn[1]);
        *(float2*)&hdst[ci] = make_float2(hn[0], hn[1]);
        if (yout) *(float2*)&yout[(long)b * yStr + jgl] = make_float2(hn[0], hn[1]);
    } else {
        cst[ci]  = cn[0];
        hdst[ci] = hn[0];
        if (yout) yout[(long)b * yStr + jgl] = hn[0];
    }

    // head partials (decoder cell1 only; JPT==1): block's 16 j -> [32b][3o]
    if (hpOut) {
        __syncthreads();                       // s_a buf0 free for reduction
#pragma unroll
        for (int jj = 0; jj < JPT; jj++) {
            int jl = j0l + jj;
            s_a[(jl * 32 + lane) * OUTn + 0] = hn[jj] * outW[jgl + jj];
            s_a[(jl * 32 + lane) * OUTn + 1] = hn[jj] * outW[Hn + jgl + jj];
            s_a[(jl * 32 + lane) * OUTn + 2] = hn[jj] * outW[2 * Hn + jgl + jj];
        }
        __syncthreads();
        if (tid < 32 * OUTn) {
            int bb = tid / OUTn, o = tid - bb * OUTn;
            float v = 0.f;
#pragma unroll
            for (int jw = 0; jw < 16; jw++)
                v += s_a[(jw * 32 + bb) * OUTn + o];
            hpOut[bb * OUTn + o] = v;
        }
    }
}

// ---------------- the persistent kernel ----------------
__global__ void __launch_bounds__(NTHR, 1) orbit_kernel(Params P)
{
    extern __shared__ float smem[];
    float* s_w    = smem;
    float* s_a    = smem + SW_FLOATS;
    float* s_bias = smem + SB_OFF;

    const int tid  = threadIdx.x;
    const int bid  = blockIdx.x;
    const int gtid = bid * NTHR + tid;
    const int gstr = NBLK * NTHR;

    // ===== Phase 0: zero encoder states AND reset group-barrier state =====
    {
        float* h0 = &g_h[0][0][0][0];
        float* c0 = &g_c[0][0][0];
        for (int e = gtid; e < 4 * Bn * Hn; e += gstr) { h0[e] = 0.f; c0[e] = 0.f; }
        for (int e = gtid; e < 16 * 32; e += gstr) { g_gcnt[e] = 0u; g_ggen[e] = 0u; }
    }
    gbar();

    // ===== Encoder: group of 8 blocks covers (dir, 64-b tile); block owns 16 j =====
    const int dir = bid >> 6;
    const int jbE = bid & 7;
    const int b0E = ((bid >> 3) & 7) * 64;
    const int j0E = jbE * 16;
    const int grp = bid >> 3;            // 0..15 (same partition for enc & dec)
    unsigned done = 0;                   // this block's completed group rounds

#pragma unroll 1
    for (int layer = 0; layer < 2; layer++) {
        int st  = layer * 2 + dir;
        if (bid < 128) {
            int kin = layer ? 2 * Hn : INn;
            pack_cell(s_w, s_bias, P.wih[st], P.whh[st], P.bih[st], P.bhh[st], kin, j0E, 0, 0);
        }
        __syncthreads();
#pragma unroll 1
        for (int s = 0; s < Tn; s++) {
            int cur = s & 1, nxt = cur ^ 1;
            if (bid < 128) {
                int t = dir ? (Tn - 1 - s) : s;
                if (layer == 0) {
                    cell_tile<64, 2>(s_w, s_a, s_bias, b0E, j0E,
                        P.x, (long)Tn * INn, (long)t * INn, INn, 0,
                        &g_h[cur][st][0][0], &g_h[nxt][st][0][0], &g_c[st][0][0],
                        g_y0 + (size_t)t * Bn * 2 * Hn + dir * Hn, 2 * Hn,
                        grp, done, false, 0, nullptr, nullptr, nullptr, nullptr, nullptr);
                } else {
                    cell_tile<64, 2>(s_w, s_a, s_bias, b0E, j0E,
                        g_y0 + (size_t)t * Bn * 2 * Hn, (long)(2 * Hn), 0L, 2 * Hn, 0,
                        &g_h[cur][st][0][0], &g_h[nxt][st][0][0], &g_c[st][0][0],
                        nullptr, 0,
                        grp, done, false, 0, nullptr, nullptr, nullptr, nullptr, nullptr);
                }
                gb_arrive(grp); done++;
            }
        }
        gbar();                       // layer boundary: y0 / final states global
    }

    // ===== Bridge: h_dec/c_dec (final enc states in buffer 0) =====
    {
        for (int idx = gtid; idx < (1 << 18); idx += gstr) {
            int j   = idx & (Hn - 1);
            int b   = (idx >> 7) & (Bn - 1);
            int l   = (idx >> 16) & 1;
            int typ = idx >> 17;
            const float* W    = typ ? P.brc_W : P.brh_W;
            const float* bias = typ ? P.brc_b : P.brh_b;
            const float* srcF = typ ? &g_c[2 * l][0][0] : &g_h[0][2 * l][0][0];
            const float* srcB = typ ? &g_c[2 * l + 1][0][0] : &g_h[0][2 * l + 1][0][0];
            const float* wr = &W[j * 2 * Hn];
            float acc = bias[j];
#pragma unroll 4
            for (int k = 0; k < Hn; k++) acc += srcF[b * Hn + k] * wr[k];
#pragma unroll 4
            for (int k = 0; k < Hn; k++) acc += srcB[b * Hn + k] * wr[Hn + k];
            if (typ) g_c[4 + l][b][j] = acc;
            else     g_h[0][4 + l][b][j] = acc;
        }
    }
    gbar();

    // ===== Decoder: group of 8 blocks covers 32-b tile; block owns 16 j =====
    // 2 rounds per step: cell0 (dep = xin partial-sum), cell1+head-partials.
    const int btD = bid >> 3;          // 0..15
    const int jbD = bid & 7;
    const int b0D = btD * 32;
    const int j0D = jbD * 16;

    if (bid < 128) {
        pack_cell(s_w, s_bias, P.wih[4], P.whh[4], P.bih[4], P.bhh[4], OUTn, j0D, 0,   0);
        pack_cell(s_w, s_bias, P.wih[5], P.whh[5], P.bih[5], P.bhh[5], Hn,   j0D, 131, 1);
    }
    __syncthreads();

#pragma unroll 1
    for (int s = 0; s < HORn; s++) {
        int cur = s & 1, nxt = cur ^ 1;
        if (bid < 128) {
            // cell 0: indep = own h4; dep = xin (sum of step s-1's head partials)
            int xmode = (s == 0) ? 2 : 1;
            const float* xv = (s == 0) ? P.start : P.out_b;
            float* pprev = (jbD == 0 && s > 0)
                         ? P.out + (size_t)(s - 1) * OUTn : nullptr;
            cell_tile<32, 1>(s_w, s_a, s_bias, b0D, j0D,
                P.start, (long)0, 0L, OUTn, 0,
                &g_h[cur][4][0][0], &g_h[nxt][4][0][0], &g_c[4][0][0], nullptr, 0,
                grp, done, true,
                xmode, &g_hp[s & 1][btD][0][0][0], xv, pprev, nullptr, nullptr);
            gb_arrive(grp); done++;

            // cell 1: indep = own h5; dep = cell0's new h4; fused head partials
            cell_tile<32, 1>(s_w, s_a, s_bias + 64, b0D, j0D,
                &g_h[nxt][4][0][0], (long)Hn, 0L, Hn, 131,
                &g_h[cur][5][0][0], &g_h[nxt][5][0][0], &g_c[5][0][0], nullptr, 0,
                grp, done, true,
                0, nullptr, nullptr, nullptr,
                &g_hp[(s + 1) & 1][btD][jbD][0][0], P.out_W);
            gb_arrive(grp); done++;
        }
    }

    // tail: write the last prediction (never consumed as xin)
    if (bid < 128) {
        gb_wait(grp, done);
        if (jbD == 0 && tid < 32 * OUTn) {
            int b = tid / OUTn, o = tid - b * OUTn;
            float v = P.out_b[o];
#pragma unroll
            for (int jb = 0; jb < 8; jb++)
                v += g_hp[HORn & 1][btD][jb][b][o];
            P.out[(size_t)(b0D + b) * HORn * OUTn + (size_t)(HORn - 1) * OUTn + o] = v;
        }
    }
}

// ---------------- launch ----------------
extern "C" void kernel_launch(void* const* d_in, const int* in_sizes, int n_in,
                              void* d_out, int out_size)
{
    (void)in_sizes; (void)n_in; (void)out_size;
    Params P;
    P.x = (const float*)d_in[0];
    const int base[6] = {1, 5, 9, 13, 21, 25};   // e0f,e0b,e1f,e1b,d0,d1
    for (int i = 0; i < 6; i++) {
        P.wih[i] = (const float*)d_in[base[i] + 0];
        P.whh[i] = (const float*)d_in[base[i] + 1];
        P.bih[i] = (const float*)d_in[base[i] + 2];
        P.bhh[i] = (const float*)d_in[base[i] + 3];
    }
    P.brh_W = (const float*)d_in[17];
    P.brh_b = (const float*)d_in[18];
    P.brc_W = (const float*)d_in[19];
    P.brc_b = (const float*)d_in[20];
    P.out_W = (const float*)d_in[29];
    P.out_b = (const float*)d_in[30];
    P.start = (const float*)d_in[31];
    P.out   = (float*)d_out;

    cudaFuncSetAttribute(orbit_kernel, cudaFuncAttributeMaxDynamicSharedMemorySize,
                         SMEM_BYTES);
    orbit_kernel<<<NBLK, NTHR, SMEM_BYTES>>>(P);
}

// round 17
// speedup vs baseline: 1.2535x; 1.2535x over previous
#include <cuda_runtime.h>

#define Tn   720
#define Bn   512
#define INn  6
#define Hn   128
#define OUTn 3
#define HORn 360
#define NBLK 148
#define NTHR 256
#define CHK  128
#define STRD 132   // [b][kk] staging stride: 33*16B -> conflict-free LDS.128

typedef unsigned long long ull;

struct Params {
    const float* x;
    const float* wih[6];   // e0f,e0b,e1f,e1b,d0,d1
    const float* whh[6];
    const float* bih[6];
    const float* bhh[6];
    const float* brh_W; const float* brh_b;
    const float* brc_W; const float* brc_b;
    const float* out_W; const float* out_b;
    const float* start;
    float* out;
};

// ---------------- scratch (device globals; no allocation allowed) ----------------
__device__ float g_y0[(size_t)Tn * Bn * 2 * Hn];      // encoder layer0 outputs [t][b][256]
__device__ float g_h[2][6][Bn][Hn];                   // double-buffered hidden state
__device__ float g_c[6][Bn][Hn];                      // cell state (in-place)
__device__ float g_hp[2][16][8][32][OUTn];            // decoder head partials [parity][grp][jb][b][o]
__device__ unsigned g_barcnt = 0;
__device__ unsigned g_bargen = 0;
__device__ unsigned g_gcnt[16 * 32];                  // monotonic arrival counts, 128B apart
__device__ unsigned g_ggen[16 * 32];                  // published completed-round counts

// ---------------- shared-memory layout (dynamic, ~167KB) ----------------
#define SW_FLOATS (387 * 64)            // weights [row][jloc*4+gate], 16 j per block
#define SA_FLOATS (64 * STRD)           // one staging buffer: 64 b x 128 kk (+pad)
#define SB_OFF    (SW_FLOATS + 2 * SA_FLOATS)
#define SMEM_BYTES ((SB_OFF + 128) * 4)

// ---------------- cp.async helpers ----------------
__device__ __forceinline__ void cp16(unsigned saddr, const float* g) {
    asm volatile("cp.async.ca.shared.global [%0], [%1], 16;" :: "r"(saddr), "l"(g));
}
#define CP_COMMIT() asm volatile("cp.async.commit_group;" ::: "memory")
#define CP_WAIT0()  asm volatile("cp.async.wait_group 0;" ::: "memory")

// ---------------- full grid barrier (phase boundaries only) ----------------
__device__ __forceinline__ void gbar() {
    __syncthreads();
    if (threadIdx.x == 0) {
        volatile unsigned* vg = &g_bargen;
        unsigned gen = *vg;
        __threadfence();
        if (atomicAdd(&g_barcnt, 1u) == NBLK - 1) {
            g_barcnt = 0;
            __threadfence();
            *vg = gen + 1;
        } else {
            while (*vg == gen) { __nanosleep(32); }
        }
        __threadfence();
    }
    __syncthreads();
}

// ---------------- split 8-block group barrier (monotonic rounds) ----------------
// Counters RESET each launch in Phase 0 (graph-replay determinism).
__device__ __forceinline__ void gb_arrive(int g) {
    __syncthreads();                           // all epilogue stores issued
    if (threadIdx.x == 0) {
        __threadfence();                       // release h/partial stores
        unsigned old = atomicAdd(&g_gcnt[g * 32], 1u);
        if (((old + 1) & 7u) == 0u) {          // 8th arrival of this round
            __threadfence();
            *(volatile unsigned*)&g_ggen[g * 32] = (old + 1) >> 3;
        }
    }
}
__device__ __forceinline__ void gb_wait(int g, unsigned target) {
    if (threadIdx.x == 0) {
        volatile unsigned* vg = &g_ggen[g * 32];
        while (*vg < target) { __nanosleep(20); }
        __threadfence();                       // acquire: invalidate L1
    }
    __syncthreads();
}

// ---------------- fast activations ----------------
__device__ __forceinline__ float sigf(float x) {
    return __fdividef(1.f, 1.f + __expf(-x));
}
__device__ __forceinline__ float tanhfast(float x) {
    return 1.f - __fdividef(2.f, __expf(2.f * x) + 1.f);
}

// ---------------- per-phase weight packing into smem ----------------
__device__ void pack_cell(float* __restrict__ s_w, float* __restrict__ s_bias,
                          const float* __restrict__ wih, const float* __restrict__ whh,
                          const float* __restrict__ bih, const float* __restrict__ bhh,
                          int Kin, int j0, int rowBase, int biasSlot)
{
    int total = (Kin + Hn) * 64;
    for (int e = threadIdx.x; e < total; e += NTHR) {
        int row = e >> 6, c = e & 63;
        int j = j0 + (c >> 2), g = c & 3;
        float v = (row < Kin) ? wih[(g * Hn + j) * Kin + row]
                              : whh[(g * Hn + j) * Hn + (row - Kin)];
        s_w[(size_t)(rowBase + row) * 64 + c] = v;
    }
    for (int e = threadIdx.x; e < 64; e += NTHR) {
        int j = j0 + (e >> 2), g = e & 3;
        s_bias[biasSlot * 64 + e] = bih[g * Hn + j] + bhh[g * Hn + j];
    }
}

struct Chunk { const float* src; long str; int kc; int wrow; };

// ---------------- fused LSTM cell tile ----------------
// Tile: BT b-rows x 16 j's with 256 threads, 8 warps. lane = b, warp = j-PAIR
// (two adjacent j per thread). Each thread owns NB b x 2 j. Activation loads
// are software-pipelined ONE QUAD AHEAD so the 29-cyc LDS latency overlaps the
// previous quad's FFMA2 stream (8 warps alone can't cover it).
template<int BT, int NB>
__device__ void cell_tile(float* __restrict__ s_w, float* __restrict__ s_a,
                          const float* __restrict__ s_bias,
                          int b0, int j0g,
                          const float* __restrict__ A, long aStr, long aOff, int Kin, int rowBase,
                          const float* __restrict__ hsrc, float* __restrict__ hdst,
                          float* __restrict__ cst, float* __restrict__ yout, int yStr,
                          int g, unsigned waitRound, bool hFirst,
                          int xinMode, const float* __restrict__ hpIn,
                          const float* __restrict__ xvec, float* __restrict__ poutPrev,
                          float* __restrict__ hpOut, const float* __restrict__ outW)
{
    const int tid  = threadIdx.x;
    const int lane = tid & 31;
    const int jq   = tid >> 5;            // j-pair index 0..7
    const int j0l  = jq * 2;              // first of this thread's two j (local)
    const int jgl  = j0g + j0l;           // global j of first
    const unsigned sa0 = (unsigned)__cvta_generic_to_shared(s_a);

    ull accL[NB][2], accH[NB][2];         // [b-block][which-j]: packed (i,f),(g,o)
    {
        ulonglong2 bj0 = *(const ulonglong2*)&s_bias[jq * 8];
        ulonglong2 bj1 = *(const ulonglong2*)&s_bias[jq * 8 + 4];
#pragma unroll
        for (int i = 0; i < NB; i++) {
            accL[i][0] = bj0.x; accH[i][0] = bj0.y;
            accL[i][1] = bj1.x; accH[i][1] = bj1.y;
        }
    }

    // ---- build chunk list, dependent chunk last ----
    Chunk ch[3]; int nch = 0;
    if (hFirst) {
        ch[nch++] = { hsrc + (long)b0 * Hn, (long)Hn, CHK, rowBase + Kin };
        ch[nch++] = { A + (long)b0 * aStr + aOff, aStr,
                      (Kin < CHK) ? Kin : CHK, rowBase };
    } else {
        for (int k0 = 0; k0 < Kin; k0 += CHK) {
            int kc = (Kin - k0 < CHK) ? (Kin - k0) : CHK;
            ch[nch].src = A + (long)b0 * aStr + aOff + k0;
            ch[nch].str = aStr; ch[nch].kc = kc; ch[nch].wrow = rowBase + k0;
            nch++;
        }
        ch[nch++] = { hsrc + (long)b0 * Hn, (long)Hn, CHK, rowBase + Kin };
    }

    auto stage_async = [&](const Chunk& c, int buf) {
#pragma unroll
        for (int u = 0; u < BT * 32 / NTHR; u++) {
            int q = tid + u * NTHR;       // quad index: b = q>>5, kq = q&31
            int b = q >> 5, kq = q & 31;
            cp16(sa0 + (unsigned)(buf * SA_FLOATS + b * STRD + kq * 4) * 4u,
                 c.src + (long)b * c.str + kq * 4);
        }
        CP_COMMIT();
    };
    // scalar staging for small chunks (K = 6 or 3); handles xin modes
    auto stage_small = [&](const Chunk& c, int buf) {
        if (xinMode == 2) {
            for (int idx = tid; idx < BT * c.kc; idx += NTHR) {
                int b = idx / c.kc, kk = idx - b * c.kc;
                s_a[buf * SA_FLOATS + b * STRD + kk] = xvec[kk];
            }
        } else if (xinMode == 1) {
            for (int idx = tid; idx < BT * OUTn; idx += NTHR) {
                int b = idx / OUTn, o = idx - b * OUTn;
                float v = xvec[o];
#pragma unroll
                for (int jb = 0; jb < 8; jb++)
                    v += hpIn[(jb * 32 + b) * OUTn + o];
                s_a[buf * SA_FLOATS + b * STRD + o] = v;
                if (poutPrev)
                    poutPrev[(size_t)(b0 + b) * HORn * OUTn + o] = v;
            }
        } else {
            for (int idx = tid; idx < BT * c.kc; idx += NTHR) {
                int b = idx / c.kc, kk = idx - b * c.kc;
                s_a[buf * SA_FLOATS + b * STRD + kk] = c.src[(long)b * c.str + kk];
            }
        }
    };

    // chunk 0 into buffer 0 (always independent — no wait needed)
    if (ch[0].kc == CHK) { stage_async(ch[0], 0); CP_WAIT0(); }
    else                 { stage_small(ch[0], 0); }
    __syncthreads();

#pragma unroll 1
    for (int i = 0; i < nch; i++) {
        if (i + 1 < nch) {
            if (i + 1 == nch - 1) gb_wait(g, waitRound);   // dep chunk: wait first
            if (ch[i + 1].kc == CHK) stage_async(ch[i + 1], (i + 1) & 1);
            else                     stage_small(ch[i + 1], (i + 1) & 1);
        }

        const int kc = ch[i].kc;
        const float* wp = s_w + (size_t)ch[i].wrow * 64 + jq * 8;
        const float* ab = s_a + (i & 1) * SA_FLOATS;
        if (kc == CHK) {
            // quad path, software-pipelined: act loads issued one quad ahead
            float4 av[NB], nv[NB];
#pragma unroll
            for (int n = 0; n < NB; n++)
                av[n] = *(const float4*)&ab[(lane + 32 * n) * STRD];
#pragma unroll 2
            for (int kq = 0; kq < CHK; kq += 4) {
                if (kq + 4 < CHK) {
#pragma unroll
                    for (int n = 0; n < NB; n++)
                        nv[n] = *(const float4*)&ab[(lane + 32 * n) * STRD + kq + 4];
                }
#pragma unroll
                for (int t = 0; t < 4; t++) {
                    ulonglong2 w0 = *(const ulonglong2*)(wp + (size_t)(kq + t) * 64);
                    ulonglong2 w1 = *(const ulonglong2*)(wp + (size_t)(kq + t) * 64 + 4);
#pragma unroll
                    for (int n = 0; n < NB; n++) {
                        float a = (t == 0) ? av[n].x : (t == 1) ? av[n].y
                                : (t == 2) ? av[n].z : av[n].w;
                        ull a2; asm("mov.b64 %0,{%1,%1};" : "=l"(a2) : "f"(a));
                        asm("fma.rn.f32x2 %0,%1,%2,%0;" : "+l"(accL[n][0]) : "l"(a2), "l"(w0.x));
                        asm("fma.rn.f32x2 %0,%1,%2,%0;" : "+l"(accH[n][0]) : "l"(a2), "l"(w0.y));
                        asm("fma.rn.f32x2 %0,%1,%2,%0;" : "+l"(accL[n][1]) : "l"(a2), "l"(w1.x));
                        asm("fma.rn.f32x2 %0,%1,%2,%0;" : "+l"(accH[n][1]) : "l"(a2), "l"(w1.y));
                    }
                }
#pragma unroll
                for (int n = 0; n < NB; n++) av[n] = nv[n];
            }
        } else {
            // scalar tail (K = 6 or 3)
            for (int kk = 0; kk < kc; kk++) {
                ulonglong2 w0 = *(const ulonglong2*)(wp + (size_t)kk * 64);
                ulonglong2 w1 = *(const ulonglong2*)(wp + (size_t)kk * 64 + 4);
#pragma unroll
                for (int n = 0; n < NB; n++) {
                    float a = ab[(lane + 32 * n) * STRD + kk];
                    ull a2; asm("mov.b64 %0,{%1,%1};" : "=l"(a2) : "f"(a));
                    asm("fma.rn.f32x2 %0,%1,%2,%0;" : "+l"(accL[n][0]) : "l"(a2), "l"(w0.x));
                    asm("fma.rn.f32x2 %0,%1,%2,%0;" : "+l"(accH[n][0]) : "l"(a2), "l"(w0.y));
                    asm("fma.rn.f32x2 %0,%1,%2,%0;" : "+l"(accL[n][1]) : "l"(a2), "l"(w1.x));
                    asm("fma.rn.f32x2 %0,%1,%2,%0;" : "+l"(accH[n][1]) : "l"(a2), "l"(w1.y));
                }
            }
        }

        if (i + 1 < nch) { CP_WAIT0(); __syncthreads(); }
    }

    // gate update — thread exclusively owns (b, jgl) and (b, jgl+1): float2 path
    float hnKeep[2] = {0.f, 0.f};
#pragma unroll
    for (int i = 0; i < NB; i++) {
        int b = b0 + lane + 32 * i;
        long ci = (long)b * Hn + jgl;
        float2 cold = *(float2*)&cst[ci];
        float gi0, gf0, gg0, go0, gi1, gf1, gg1, go1;
        asm("mov.b64 {%0,%1},%2;" : "=f"(gi0), "=f"(gf0) : "l"(accL[i][0]));
        asm("mov.b64 {%0,%1},%2;" : "=f"(gg0), "=f"(go0) : "l"(accH[i][0]));
        asm("mov.b64 {%0,%1},%2;" : "=f"(gi1), "=f"(gf1) : "l"(accL[i][1]));
        asm("mov.b64 {%0,%1},%2;" : "=f"(gg1), "=f"(go1) : "l"(accH[i][1]));
        float2 cn, hn;
        cn.x = sigf(gf0) * cold.x + sigf(gi0) * tanhfast(gg0);
        cn.y = sigf(gf1) * cold.y + sigf(gi1) * tanhfast(gg1);
        hn.x = sigf(go0) * tanhfast(cn.x);
        hn.y = sigf(go1) * tanhfast(cn.y);
        *(float2*)&cst[ci]  = cn;
        *(float2*)&hdst[ci] = hn;
        hnKeep[0] = hn.x; hnKeep[1] = hn.y;
        if (yout) *(float2*)&yout[(long)b * yStr + jgl] = hn;
    }

    // head partials (decoder cell1 only; NB==1): block's 16 j -> [32b][3o]
    if (hpOut) {
        __syncthreads();                       // s_a buf0 free for reduction
#pragma unroll
        for (int jj = 0; jj < 2; jj++) {
            int jl = j0l + jj;
            s_a[(jl * 32 + lane) * OUTn + 0] = hnKeep[jj] * outW[jgl + jj];
            s_a[(jl * 32 + lane) * OUTn + 1] = hnKeep[jj] * outW[Hn + jgl + jj];
            s_a[(jl * 32 + lane) * OUTn + 2] = hnKeep[jj] * outW[2 * Hn + jgl + jj];
        }
        __syncthreads();
        if (tid < 32 * OUTn) {
            int b = tid / OUTn, o = tid - b * OUTn;
            float v = 0.f;
#pragma unroll
            for (int jw = 0; jw < 16; jw++)
                v += s_a[(jw * 32 + b) * OUTn + o];
            hpOut[b * OUTn + o] = v;
        }
    }
}

// ---------------- the persistent kernel ----------------
__global__ void __launch_bounds__(NTHR, 1) orbit_kernel(Params P)
{
    extern __shared__ float smem[];
    float* s_w    = smem;
    float* s_a    = smem + SW_FLOATS;
    float* s_bias = smem + SB_OFF;

    const int tid  = threadIdx.x;
    const int bid  = blockIdx.x;
    const int gtid = bid * NTHR + tid;
    const int gstr = NBLK * NTHR;

    // ===== Phase 0: zero encoder states AND reset group-barrier state =====
    {
        float* h0 = &g_h[0][0][0][0];
        float* c0 = &g_c[0][0][0];
        for (int e = gtid; e < 4 * Bn * Hn; e += gstr) { h0[e] = 0.f; c0[e] = 0.f; }
        for (int e = gtid; e < 16 * 32; e += gstr) { g_gcnt[e] = 0u; g_ggen[e] = 0u; }
    }
    gbar();

    // ===== Encoder: group of 8 blocks covers (dir, 64-b tile); block owns 16 j =====
    const int dir = bid >> 6;
    const int jbE = bid & 7;
    const int b0E = ((bid >> 3) & 7) * 64;
    const int j0E = jbE * 16;
    const int grp = bid >> 3;            // 0..15 (same partition for enc & dec)
    unsigned done = 0;                   // this block's completed group rounds

#pragma unroll 1
    for (int layer = 0; layer < 2; layer++) {
        int st  = layer * 2 + dir;
        if (bid < 128) {
            int kin = layer ? 2 * Hn : INn;
            pack_cell(s_w, s_bias, P.wih[st], P.whh[st], P.bih[st], P.bhh[st], kin, j0E, 0, 0);
        }
        __syncthreads();
#pragma unroll 1
        for (int s = 0; s < Tn; s++) {
            int cur = s & 1, nxt = cur ^ 1;
            if (bid < 128) {
                int t = dir ? (Tn - 1 - s) : s;
                if (layer == 0) {
                    cell_tile<64, 2>(s_w, s_a, s_bias, b0E, j0E,
                        P.x, (long)Tn * INn, (long)t * INn, INn, 0,
                        &g_h[cur][st][0][0], &g_h[nxt][st][0][0], &g_c[st][0][0],
                        g_y0 + (size_t)t * Bn * 2 * Hn + dir * Hn, 2 * Hn,
                        grp, done, false,
                        0, nullptr, nullptr, nullptr, nullptr, nullptr);
                } else {
                    cell_tile<64, 2>(s_w, s_a, s_bias, b0E, j0E,
                        g_y0 + (size_t)t * Bn * 2 * Hn, (long)(2 * Hn), 0L, 2 * Hn, 0,
                        &g_h[cur][st][0][0], &g_h[nxt][st][0][0], &g_c[st][0][0],
                        nullptr, 0,
                        grp, done, false,
                        0, nullptr, nullptr, nullptr, nullptr, nullptr);
                }
                gb_arrive(grp); done++;
            }
        }
        gbar();                       // layer boundary: y0 / final states global
    }

    // ===== Bridge: h_dec/c_dec (final enc states in buffer 0) =====
    {
        for (int idx = gtid; idx < (1 << 18); idx += gstr) {
            int j   = idx & (Hn - 1);
            int b   = (idx >> 7) & (Bn - 1);
            int l   = (idx >> 16) & 1;
            int typ = idx >> 17;
            const float* W    = typ ? P.brc_W : P.brh_W;
            const float* bias = typ ? P.brc_b : P.brh_b;
            const float* srcF = typ ? &g_c[2 * l][0][0] : &g_h[0][2 * l][0][0];
            const float* srcB = typ ? &g_c[2 * l + 1][0][0] : &g_h[0][2 * l + 1][0][0];
            const float* wr = &W[j * 2 * Hn];
            float acc = bias[j];
#pragma unroll 4
            for (int k = 0; k < Hn; k++) acc += srcF[b * Hn + k] * wr[k];
#pragma unroll 4
            for (int k = 0; k < Hn; k++) acc += srcB[b * Hn + k] * wr[Hn + k];
            if (typ) g_c[4 + l][b][j] = acc;
            else     g_h[0][4 + l][b][j] = acc;
        }
    }
    gbar();

    // ===== Decoder: group of 8 blocks covers 32-b tile; block owns 16 j =====
    // 2 rounds per step: cell0 (dep = xin partial-sum), cell1+head-partials.
    const int btD = bid >> 3;          // 0..15
    const int jbD = bid & 7;
    const int b0D = btD * 32;
    const int j0D = jbD * 16;

    if (bid < 128) {
        pack_cell(s_w, s_bias, P.wih[4], P.whh[4], P.bih[4], P.bhh[4], OUTn, j0D, 0,   0);
        pack_cell(s_w, s_bias, P.wih[5], P.whh[5], P.bih[5], P.bhh[5], Hn,   j0D, 131, 1);
    }
    __syncthreads();

#pragma unroll 1
    for (int s = 0; s < HORn; s++) {
        int cur = s & 1, nxt = cur ^ 1;
        if (bid < 128) {
            // cell 0: indep = own h4; dep = xin (sum of step s-1's head partials)
            int xmode = (s == 0) ? 2 : 1;
            const float* xv = (s == 0) ? P.start : P.out_b;
            float* pprev = (jbD == 0 && s > 0)
                         ? P.out + (size_t)(s - 1) * OUTn : nullptr;
            cell_tile<32, 1>(s_w, s_a, s_bias, b0D, j0D,
                P.start, (long)0, 0L, OUTn, 0,
                &g_h[cur][4][0][0], &g_h[nxt][4][0][0], &g_c[4][0][0], nullptr, 0,
                grp, done, true,
                xmode, &g_hp[s & 1][btD][0][0][0], xv, pprev, nullptr, nullptr);
            gb_arrive(grp); done++;

            // cell 1: indep = own h5; dep = cell0's new h4; fused head partials
            cell_tile<32, 1>(s_w, s_a, s_bias + 64, b0D, j0D,
                &g_h[nxt][4][0][0], (long)Hn, 0L, Hn, 131,
                &g_h[cur][5][0][0], &g_h[nxt][5][0][0], &g_c[5][0][0], nullptr, 0,
                grp, done, true,
                0, nullptr, nullptr, nullptr,
                &g_hp[(s + 1) & 1][btD][jbD][0][0], P.out_W);
            gb_arrive(grp); done++;
        }
    }

    // tail: write the last prediction (never consumed as xin)
    if (bid < 128) {
        gb_wait(grp, done);
        if (jbD == 0 && tid < 32 * OUTn) {
            int b = tid / OUTn, o = tid - b * OUTn;
            float v = P.out_b[o];
#pragma unroll
            for (int jb = 0; jb < 8; jb++)
                v += g_hp[HORn & 1][btD][jb][b][o];
            P.out[(size_t)(b0D + b) * HORn * OUTn + (size_t)(HORn - 1) * OUTn + o] = v;
        }
    }
}

// ---------------- launch ----------------
extern "C" void kernel_launch(void* const* d_in, const int* in_sizes, int n_in,
                              void* d_out, int out_size)
{
    (void)in_sizes; (void)n_in; (void)out_size;
    Params P;
    P.x = (const float*)d_in[0];
    const int base[6] = {1, 5, 9, 13, 21, 25};   // e0f,e0b,e1f,e1b,d0,d1
    for (int i = 0; i < 6; i++) {
        P.wih[i] = (const float*)d_in[base[i] + 0];
        P.whh[i] = (const float*)d_in[base[i] + 1];
        P.bih[i] = (const float*)d_in[base[i] + 2];
        P.bhh[i] = (const float*)d_in[base[i] + 3];
    }
    P.brh_W = (const float*)d_in[17];
    P.brh_b = (const float*)d_in[18];
    P.brc_W = (const float*)d_in[19];
    P.brc_b = (const float*)d_in[20];
    P.out_W = (const float*)d_in[29];
    P.out_b = (const float*)d_in[30];
    P.start = (const float*)d_in[31];
    P.out   = (float*)d_out;

    cudaFuncSetAttribute(orbit_kernel, cudaFuncAttributeMaxDynamicSharedMemorySize,
                         SMEM_BYTES);
    orbit_kernel<<<NBLK, NTHR, SMEM_BYTES>>>(P);
}